// round 1
// baseline (speedup 1.0000x reference)
#include <cuda_runtime.h>
#include <cstdint>

#define BB    16
#define CC    512
#define NPOS  400
#define HID   256
#define NEMB  30
#define LOCN  8
#define TT    201
#define OUTW  38      // NEMB + LOCN
#define XDIM  542     // CC + NEMB
#define RCL   8       // CTAs per cluster
#define NLOC  50      // NPOS / RCL
#define JLOC  32      // HID / RCL
#define CCH   64      // CC / RCL
#define NTHR  1024
#define NWARP 32
#define FSTR  516     // padded feat row stride (floats)
#define HSTR  256

// ---------------- device scratch (no allocations allowed) ----------------
__device__ float g_i2hT[CC * HID];       // transposed i2h: [c][h]
__device__ float g_Wcomb[OUTW * HID];    // fused output head weights
__device__ float g_bcomb[OUTW];          // fused output head biases

// ---------------- helpers ----------------
__device__ __forceinline__ uint32_t smem_u32(const void* p) {
    return (uint32_t)__cvta_generic_to_shared(p);
}
__device__ __forceinline__ uint32_t mapa_u32(uint32_t addr, uint32_t rank) {
    uint32_t r;
    asm("mapa.shared::cluster.u32 %0, %1, %2;" : "=r"(r) : "r"(addr), "r"(rank));
    return r;
}
__device__ __forceinline__ float ld_dsm(uint32_t a) {
    float v;
    asm volatile("ld.shared::cluster.f32 %0, [%1];" : "=f"(v) : "r"(a));
    return v;
}
__device__ __forceinline__ void st_dsm(uint32_t a, float v) {
    asm volatile("st.shared::cluster.f32 [%0], %1;" :: "r"(a), "f"(v));
}
#define CLUSTER_SYNC() do { \
    asm volatile("barrier.cluster.arrive.aligned;" ::: "memory"); \
    asm volatile("barrier.cluster.wait.aligned;"   ::: "memory"); } while (0)

__device__ __forceinline__ float sigmoidf_(float x) {
    return __fdividef(1.f, 1.f + __expf(-x));
}
__device__ __forceinline__ float tanhf_(float x) {
    float cx = fminf(fmaxf(x, -15.f), 15.f);
    float e = __expf(2.f * cx);
    return __fdividef(e - 1.f, e + 1.f);
}

// ---------------- prep kernel: fuse output heads + transpose i2h ----------------
__global__ void prep_kernel(const float* __restrict__ i2h,
                            const float* __restrict__ sg1w, const float* __restrict__ sg1b,
                            const float* __restrict__ sg2w, const float* __restrict__ sg2b,
                            const float* __restrict__ lg1w, const float* __restrict__ lg1b,
                            const float* __restrict__ lg2w, const float* __restrict__ lg2b) {
    int blk = blockIdx.x;
    int tid = threadIdx.x;
    if (blk < OUTW) {
        const float *W2, *W1, *b1, *b2;
        int row;
        if (blk < NEMB) { row = blk;        W2 = sg2w; W1 = sg1w; b1 = sg1b; b2 = sg2b; }
        else            { row = blk - NEMB; W2 = lg2w; W1 = lg1w; b1 = lg1b; b2 = lg2b; }
        float acc = 0.f;
        for (int k = 0; k < HID; k++)
            acc += W2[row * HID + k] * W1[k * HID + tid];
        g_Wcomb[blk * HID + tid] = acc;
        __shared__ float red[HID];
        red[tid] = W2[row * HID + tid] * b1[tid];
        __syncthreads();
        for (int s = HID / 2; s > 0; s >>= 1) {
            if (tid < s) red[tid] += red[tid + s];
            __syncthreads();
        }
        if (tid == 0) g_bcomb[blk] = red[0] + b2[row];
    } else {
        int c = blk - OUTW;                 // 0..511
        g_i2hT[c * HID + tid] = i2h[tid * CC + c];
    }
}

// ---------------- main persistent cluster kernel ----------------
struct __align__(16) Smem {
    float feat[NLOC * FSTR];     // local feat slice [nl][c]
    float hproj[NLOC * HSTR];    // local i2h(feat) slice [nl][h]
    float score[HID];
    float pp[HID];               // full prev_proj (assembled)
    float ctx[CC];               // full normalized context (assembled)
    float part_ctx[CC];          // my unnormalized partial context
    float red[CCH * RCL];        // reduction staging
    float chunk[CCH];            // my reduced+normalized ctx chunk
    float hid[2][HID];           // double-buffered hidden state
    float pp_part[JLOC];         // my prev_proj slice
    float wexp[NLOC];            // exp(e_n) for local rows
    float es;                    // my partial expsum
    float es_buf[RCL];
};

__global__ void __launch_bounds__(NTHR, 1) __cluster_dims__(RCL, 1, 1)
sla_kernel(const float* __restrict__ fea, const int* __restrict__ structure,
           const float* __restrict__ h2h_w, const float* __restrict__ h2h_b,
           const float* __restrict__ score_w,
           const float* __restrict__ wih, const float* __restrict__ bih,
           const float* __restrict__ whh, const float* __restrict__ bhh,
           float* __restrict__ out) {
    extern __shared__ char smem_raw[];
    Smem* sm = (Smem*)smem_raw;
    const int tid  = threadIdx.x;
    const int lane = tid & 31;
    const int wid  = tid >> 5;
    const int b    = blockIdx.x >> 3;
    const int r    = blockIdx.x & 7;

    // ---- prologue: load feat slice, score, zero hidden ----
    {
        const float* fb = fea + (size_t)b * CC * NPOS;
        for (int idx = tid; idx < NLOC * CC; idx += NTHR) {
            int c  = idx / NLOC;
            int nl = idx - c * NLOC;
            sm->feat[nl * FSTR + c] = fb[c * NPOS + r * NLOC + nl];
        }
        for (int i = tid; i < HID; i += NTHR) {
            sm->score[i]  = score_w[i];
            sm->hid[0][i] = 0.f;
            sm->hid[1][i] = 0.f;
        }
    }
    __syncthreads();

    // ---- prologue: hproj[nl][h] = sum_c feat[nl][c] * i2h[h][c] ----
    {
        int h  = tid & 255;
        int g  = tid >> 8;            // 0..3
        int n0 = g * 13;
        float acc[13];
        #pragma unroll
        for (int i = 0; i < 13; i++) acc[i] = 0.f;
        for (int c = 0; c < CC; c += 4) {
            float w0 = g_i2hT[(c + 0) * HID + h];
            float w1 = g_i2hT[(c + 1) * HID + h];
            float w2 = g_i2hT[(c + 2) * HID + h];
            float w3 = g_i2hT[(c + 3) * HID + h];
            #pragma unroll
            for (int i = 0; i < 13; i++) {
                int n = n0 + i;
                if (n < NLOC) {
                    float4 f = *(const float4*)&sm->feat[n * FSTR + c];
                    acc[i] += f.x * w0 + f.y * w1 + f.z * w2 + f.w * w3;
                }
            }
        }
        #pragma unroll
        for (int i = 0; i < 13; i++) {
            int n = n0 + i;
            if (n < NLOC) sm->hproj[n * HSTR + h] = acc[i];
        }
    }
    // initial prev_proj (hidden = 0): just the bias slice
    if (tid < JLOC) sm->pp_part[tid] = h2h_b[r * JLOC + tid];
    CLUSTER_SYNC();

    // ---- decode loop ----
    for (int t = 0; t < TT; t++) {
        const int cur = t & 1, nxt = cur ^ 1;

        // assemble full prev_proj from peers
        if (tid < HID) {
            int p = tid >> 5, idx = tid & 31;
            sm->pp[tid] = ld_dsm(mapa_u32(smem_u32(&sm->pp_part[idx]), p));
        }
        __syncthreads();

        // attention scores: e_n = score . tanh(hproj_n + pp), w_n = exp(e_n)
        for (int n = wid; n < NLOC; n += NWARP) {
            float acc = 0.f;
            #pragma unroll
            for (int q = 0; q < 2; q++) {
                int h4 = lane * 2 + q;
                float4 hv = ((const float4*)&sm->hproj[n * HSTR])[h4];
                float4 pv = ((const float4*)sm->pp)[h4];
                float4 sv = ((const float4*)sm->score)[h4];
                acc += tanhf_(hv.x + pv.x) * sv.x;
                acc += tanhf_(hv.y + pv.y) * sv.y;
                acc += tanhf_(hv.z + pv.z) * sv.z;
                acc += tanhf_(hv.w + pv.w) * sv.w;
            }
            #pragma unroll
            for (int o = 16; o > 0; o >>= 1) acc += __shfl_xor_sync(0xffffffffu, acc, o);
            if (lane == 0) sm->wexp[n] = __expf(acc);
        }
        __syncthreads();

        // local expsum (warp 0) + partial context (threads 0..511)
        if (wid == 0) {
            float v = (lane < NLOC) ? sm->wexp[lane] : 0.f;
            if (lane + 32 < NLOC) v += sm->wexp[lane + 32];
            #pragma unroll
            for (int o = 16; o > 0; o >>= 1) v += __shfl_xor_sync(0xffffffffu, v, o);
            if (lane == 0) sm->es = v;
        }
        if (tid < CC) {
            float a0 = 0.f;
            #pragma unroll 5
            for (int n = 0; n < NLOC; n++)
                a0 += sm->wexp[n] * sm->feat[n * FSTR + tid];
            sm->part_ctx[tid] = a0;
        }
        CLUSTER_SYNC();   // S2

        // cross-CTA reduce: my chunk c in [r*64, r*64+64)
        if (tid < CC) {
            int cl = tid >> 3, p = tid & 7;
            sm->red[cl * RCL + p] =
                ld_dsm(mapa_u32(smem_u32(&sm->part_ctx[r * CCH + cl]), p));
        }
        if (tid >= CC && tid < CC + RCL) {
            int p = tid - CC;
            sm->es_buf[p] = ld_dsm(mapa_u32(smem_u32(&sm->es), p));
        }
        __syncthreads();
        if (tid < CCH) {
            float s = 0.f, et = 0.f;
            #pragma unroll
            for (int p = 0; p < RCL; p++) { s += sm->red[tid * RCL + p]; et += sm->es_buf[p]; }
            sm->chunk[tid] = __fdividef(s, et);
        }
        __syncthreads();
        // all-gather: push my chunk into every CTA's ctx
        if (tid < CC) {
            int cl = tid >> 3, p = tid & 7;
            st_dsm(mapa_u32(smem_u32(&sm->ctx[r * CCH + cl]), p), sm->chunk[cl]);
        }
        CLUSTER_SYNC();   // S3

        // GRU: warp `wid` computes hidden unit j = r*32 + wid
        {
            const int ch = structure[b * TT + t];
            const int j  = r * JLOC + wid;
            const float* wr = wih + (size_t)j * XDIM;
            const float* wz = wih + (size_t)(j + HID) * XDIM;
            const float* wn = wih + (size_t)(j + 2 * HID) * XDIM;
            float ar = 0.f, az = 0.f, an = 0.f;
            #pragma unroll
            for (int k = lane; k < CC; k += 32) {
                float cv = sm->ctx[k];
                ar += wr[k] * cv; az += wz[k] * cv; an += wn[k] * cv;
            }
            const float* vr = whh + (size_t)j * HID;
            const float* vz = whh + (size_t)(j + HID) * HID;
            const float* vn = whh + (size_t)(j + 2 * HID) * HID;
            float hr = 0.f, hz = 0.f, hn = 0.f;
            #pragma unroll
            for (int k = lane; k < HID; k += 32) {
                float hv = sm->hid[cur][k];
                hr += vr[k] * hv; hz += vz[k] * hv; hn += vn[k] * hv;
            }
            #pragma unroll
            for (int o = 16; o > 0; o >>= 1) {
                ar += __shfl_xor_sync(0xffffffffu, ar, o);
                az += __shfl_xor_sync(0xffffffffu, az, o);
                an += __shfl_xor_sync(0xffffffffu, an, o);
                hr += __shfl_xor_sync(0xffffffffu, hr, o);
                hz += __shfl_xor_sync(0xffffffffu, hz, o);
                hn += __shfl_xor_sync(0xffffffffu, hn, o);
            }
            float hnew = 0.f;
            if (lane == 0) {
                float gir = ar + wr[CC + ch] + bih[j];
                float giz = az + wz[CC + ch] + bih[j + HID];
                float gin = an + wn[CC + ch] + bih[j + 2 * HID];
                float ghr = hr + bhh[j];
                float ghz = hz + bhh[j + HID];
                float ghn = hn + bhh[j + 2 * HID];
                float rg = sigmoidf_(gir + ghr);
                float zg = sigmoidf_(giz + ghz);
                float ng = tanhf_(gin + rg * ghn);
                hnew = (1.f - zg) * ng + zg * sm->hid[cur][j];
            }
            hnew = __shfl_sync(0xffffffffu, hnew, 0);
            if (lane < RCL)
                st_dsm(mapa_u32(smem_u32(&sm->hid[nxt][j]), lane), hnew);
        }
        CLUSTER_SYNC();   // S4 — hid[nxt] complete everywhere

        // outputs (fused heads) + prev_proj for next step
        {
            const float* hv = sm->hid[nxt];
            if (wid < 5) {
                int ow = r + 8 * wid;
                if (ow < OUTW) {
                    const float* wrow = g_Wcomb + ow * HID;
                    float a0 = 0.f;
                    #pragma unroll
                    for (int k = lane; k < HID; k += 32) a0 += wrow[k] * hv[k];
                    #pragma unroll
                    for (int o = 16; o > 0; o >>= 1) a0 += __shfl_xor_sync(0xffffffffu, a0, o);
                    if (lane == 0) {
                        a0 += g_bcomb[ow];
                        if (ow >= NEMB) a0 = sigmoidf_(a0);
                        out[((size_t)b * TT + t) * OUTW + ow] = a0;
                    }
                }
            }
            int j = r * JLOC + wid;
            const float* hrow = h2h_w + (size_t)j * HID;
            float a0 = 0.f;
            #pragma unroll
            for (int k = lane; k < HID; k += 32) a0 += hrow[k] * hv[k];
            #pragma unroll
            for (int o = 16; o > 0; o >>= 1) a0 += __shfl_xor_sync(0xffffffffu, a0, o);
            if (lane == 0) sm->pp_part[wid] = a0 + h2h_b[j];
        }
        CLUSTER_SYNC();   // S1 for next iteration
    }
}

// ---------------- launch ----------------
extern "C" void kernel_launch(void* const* d_in, const int* in_sizes, int n_in,
                              void* d_out, int out_size) {
    const float* fea       = (const float*)d_in[0];
    const int*   structure = (const int*)  d_in[1];
    const float* i2h_w     = (const float*)d_in[2];
    const float* h2h_w     = (const float*)d_in[3];
    const float* h2h_b     = (const float*)d_in[4];
    const float* score_w   = (const float*)d_in[5];
    const float* gru_wih   = (const float*)d_in[6];
    const float* gru_bih   = (const float*)d_in[7];
    const float* gru_whh   = (const float*)d_in[8];
    const float* gru_bhh   = (const float*)d_in[9];
    const float* sg1_w     = (const float*)d_in[10];
    const float* sg1_b     = (const float*)d_in[11];
    const float* sg2_w     = (const float*)d_in[12];
    const float* sg2_b     = (const float*)d_in[13];
    const float* lg1_w     = (const float*)d_in[14];
    const float* lg1_b     = (const float*)d_in[15];
    const float* lg2_w     = (const float*)d_in[16];
    const float* lg2_b     = (const float*)d_in[17];
    float* out = (float*)d_out;

    prep_kernel<<<OUTW + CC, HID>>>(i2h_w, sg1_w, sg1_b, sg2_w, sg2_b,
                                    lg1_w, lg1_b, lg2_w, lg2_b);

    cudaFuncSetAttribute(sla_kernel, cudaFuncAttributeMaxDynamicSharedMemorySize,
                         (int)sizeof(Smem));
    sla_kernel<<<BB * RCL, NTHR, sizeof(Smem)>>>(
        fea, structure, h2h_w, h2h_b, score_w,
        gru_wih, gru_bih, gru_whh, gru_bhh, out);
}